// round 11
// baseline (speedup 1.0000x reference)
#include <cuda_runtime.h>
#include <cstdint>
#define T_STEPS 200
typedef unsigned long long u64t;

// ---------------- device scratch ----------------
__device__ float g_pp[2 * 288 * 64 * 4];      // pooled acts, 2 slots [slot][k4][b][4]
__device__ float g_s3b[3 * 64 * 256];          // conv3 spikes [slot][b][oc]
__device__ float g_srb[2 * 64 * 256];          // rec spikes   [buf][b][oc]
__device__ float g_sfb[2 * 64 * 128];          // fc1 spikes   [buf][b][row]
__device__ unsigned g_cnt[8 * 32];
__device__ unsigned g_gen[8 * 32];

__device__ __forceinline__ void gridbar_g(int grp, unsigned n) {
    __syncthreads();
    if (threadIdx.x == 0) {
        unsigned* cnt = &g_cnt[grp * 32];
        unsigned* gen = &g_gen[grp * 32];
        unsigned g;
        asm volatile("ld.acquire.gpu.u32 %0, [%1];" : "=r"(g) : "l"(gen));
        unsigned prev;
        asm volatile("atom.acq_rel.gpu.add.u32 %0, [%1], 1;"
                     : "=r"(prev) : "l"(cnt) : "memory");
        if (prev == n - 1u) {
            asm volatile("st.relaxed.gpu.u32 [%0], %1;" :: "l"(cnt), "r"(0u) : "memory");
            asm volatile("st.release.gpu.u32 [%0], %1;" :: "l"(gen), "r"(g + 1u) : "memory");
        } else {
            unsigned cur;
            do {
                asm volatile("ld.acquire.gpu.u32 %0, [%1];" : "=r"(cur) : "l"(gen));
            } while (cur == g);
        }
    }
    __syncthreads();
}
__device__ __forceinline__ u64t pk2(float lo, float hi) {
    u64t r; asm("mov.b64 %0, {%1, %2};" : "=l"(r) : "f"(lo), "f"(hi)); return r;
}
__device__ __forceinline__ void upk2(u64t v, float& lo, float& hi) {
    asm("mov.b64 {%0, %1}, %2;" : "=f"(lo), "=f"(hi) : "l"(v));
}
__device__ __forceinline__ u64t fma2(u64t a, u64t b, u64t c) {
    u64t d; asm("fma.rn.f32x2 %0, %1, %2, %3;" : "=l"(d) : "l"(a), "l"(b), "l"(c)); return d;
}
__device__ __forceinline__ void lif_update(float psp, float& cur, float& volt, float& spk) {
    cur  = __fadd_rn(__fmul_rn(0.5f, cur), psp);
    volt = __fadd_rn(__fmul_rn(__fmul_rn(0.75f, volt), __fadd_rn(1.f, -spk)), cur);
    spk  = (volt > 0.5f) ? 1.f : 0.f;
}

// ---------------- SMEM layout (floats) ----------------
#define S_XS    0        // 100
#define S_W1S   100      // 576
#define S_B1S   676      // 64
#define S_B2S   740      // 64
#define S_S1S   804      // 4160
#define S_S2S   4964     // 2304
#define S_W2P   7268     // 36864
#define S_B3    44132    // 16
#define S_TCB   44148    // 48
#define S_RECB  44196    // 16
#define S_F1B   44212    // 16
#define S_F2S   44228    // 256
#define S_TSW   44484    // 200
#define S_TOT   44684    // 178736 bytes

// ============================================================================
// Fused kernel: 128 CTAs x 128 threads.  Group g = CTAs [16g,16g+16).
// A-role: (b = 8g + (c16>>1), h = c16&1)   B-role: (og = c16, b-tile [8g,8g+8))
// Iteration s: phaseA(t=s) overlapped with phaseB conv3(t=s-1); then barriers,
// tc/rec(t=s-1), fc1(t=s-1), fc2(t=s-2).
// ============================================================================
__global__ __launch_bounds__(128, 1)
void fused_kernel(const float* __restrict__ input,
                  const float* __restrict__ w1, const float* __restrict__ b1,
                  const float* __restrict__ w2, const float* __restrict__ b2,
                  const float* __restrict__ w3, const float* __restrict__ b3,
                  const float* __restrict__ tcw, const float* __restrict__ tcb,
                  const float* __restrict__ recw, const float* __restrict__ recb,
                  const float* __restrict__ f1w, const float* __restrict__ f1b,
                  const float* __restrict__ f2w, const float* __restrict__ tsw,
                  float* __restrict__ out)
{
    extern __shared__ float sm[];
    float* xs   = sm + S_XS;
    float* w1s  = sm + S_W1S;
    float* b1s  = sm + S_B1S;
    float* b2s  = sm + S_B2S;
    float* s1s  = sm + S_S1S;
    float* s2s  = sm + S_S2S;
    float* w2p  = sm + S_W2P;
    float* b3s  = sm + S_B3;
    float* tcbs = sm + S_TCB;
    float* recbs= sm + S_RECB;
    float* f1bs = sm + S_F1B;
    float* f2s  = sm + S_F2S;
    float* tsws = sm + S_TSW;

    const int tid = threadIdx.x;
    const int cta = blockIdx.x;
    const int c16 = cta & 15, grp = cta >> 4;
    // A-role
    const int bA = grp * 8 + (c16 >> 1), h = c16 & 1;
    // B-role
    const int og = c16;
    const int ol = tid >> 3, blB = tid & 7;
    const int bB = grp * 8 + blB;
    const int rowB = og * 16 + ol;

    // ---- one-time staging ----
    for (int i = tid; i < 36864; i += 128) {
        int oc = i / 576, r = i - oc * 576;
        w2p[(r * 32 + (oc >> 1)) * 2 + (oc & 1)] = w2[h * 36864 + i];
    }
    for (int i = tid; i < 576; i += 128) w1s[i] = w1[i];
    if (tid < 64) { b1s[tid] = b1[tid]; b2s[tid] = b2[h * 64 + tid]; }
    for (int i = tid; i < 4160; i += 128) s1s[i] = 0.f;
    for (int i = tid; i < 2304; i += 128) s2s[i] = 0.f;
    if (tid < 16) {
        b3s[tid] = b3[og * 16 + tid];
        recbs[tid] = recb[og * 16 + tid];
        if (og < 8) f1bs[tid] = f1b[og * 16 + tid];
    }
    if (tid < 48) tcbs[tid] = tcb[(tid >> 4) * 256 + og * 16 + (tid & 15)];
    for (int i = tid; i < 256; i += 128) f2s[i] = f2w[i];
    for (int i = tid; i < 200; i += 128) tsws[i] = tsw[i];
    __syncthreads();

    // A LIF states (conv1 per 2 oc x 16 pos; conv2 per 2 oc x 9 pos)
    const int p = tid >> 2, q = tid & 3;
    const int qy = q >> 1, qx = q & 1;
    const int y0a = qy * 4, x0a = qx * 4, y0b = qy * 3, x0b = qx * 3;
    float c1[2][16], v1[2][16], c2[2][9], v2[2][9], sp2[2][9];
#pragma unroll
    for (int o = 0; o < 2; ++o) {
#pragma unroll
        for (int i = 0; i < 16; ++i) { c1[o][i] = 0.f; v1[o][i] = 0.f; }
#pragma unroll
        for (int i = 0; i < 9; ++i) { c2[o][i] = 0.f; v2[o][i] = 0.f; sp2[o][i] = 0.f; }
    }
    // B LIF states
    float cur3 = 0.f, volt3 = 0.f, spk3 = 0.f;
    float curt = 0.f, voltt = 0.f, spkt = 0.f;
    float curr = 0.f, voltr = 0.f, spkr = 0.f;
    float curf = 0.f, voltf = 0.f, spkf = 0.f;
    float outacc = 0.f;

    const float* xin = input + (size_t)bA * 20000;
    const float* wb3 = w3 + (size_t)rowB * 1152;

    for (int s = 0; s <= T_STEPS; ++s) {
        const int tB = s - 1;
        const bool doA = (s < T_STEPS);
        const bool doB = (tB >= 0);

        // ---------- A: frame + conv1 ----------
        if (doA) {
            if (tid < 100) xs[tid] = xin[tid * 200 + s];
            __syncthreads();
#pragma unroll
            for (int o = 0; o < 2; ++o) {
                const int occ = 2 * p + o;
                const float bb = b1s[occ];
                const float* wv = w1s + occ * 9;
#pragma unroll
                for (int iy = 0; iy < 4; ++iy)
#pragma unroll
                    for (int ix = 0; ix < 4; ++ix) {
                        const int y = y0a + iy, x = x0a + ix;
                        float a = 0.f;
#pragma unroll
                        for (int ky = 0; ky < 3; ++ky)
#pragma unroll
                            for (int kx = 0; kx < 3; ++kx)
                                a = __fmaf_rn(xs[(y + ky) * 10 + (x + kx)],
                                              wv[ky * 3 + kx], a);
                        const float psp = __fadd_rn(a, bb);
                        const int i = iy * 4 + ix, sidx = occ * 65 + y * 8 + x;
                        float sp = s1s[sidx];
                        lif_update(psp, c1[o][i], v1[o][i], sp);
                        s1s[sidx] = sp;
                    }
            }
            __syncthreads();
        }

        // ---------- fused conv2 (A) + conv3 (B): 8 interleaved blocks ----------
        float a3 = 0.f;
        const float* xb3 = g_pp + (size_t)(tB & 1) * 73728 + bB * 4;
        u64t acc2[9];
#pragma unroll
        for (int j = 0; j < 9; ++j) acc2[j] = 0ull;

        for (int blk = 0; blk < 8; ++blk) {
            // conv3 sub-block: 36 k4-groups, serial chain, L2-hot ldcg
            if (doB) {
#pragma unroll 6
                for (int k4 = blk * 36; k4 < blk * 36 + 36; ++k4) {
                    float4 x = __ldcg((const float4*)(xb3 + (size_t)k4 * 256));
                    float4 w = __ldcg((const float4*)(wb3 + k4 * 4));
                    a3 = __fmaf_rn(w.x, x.x, a3);
                    a3 = __fmaf_rn(w.y, x.y, a3);
                    a3 = __fmaf_rn(w.z, x.z, a3);
                    a3 = __fmaf_rn(w.w, x.w, a3);
                }
            }
            // conv2 sub-block: 8 ics (ascending -> chain order preserved)
            if (doA) {
#pragma unroll 2
                for (int ici = 0; ici < 8; ++ici) {
                    const int ic = blk * 8 + ici;
                    u64t ins[5][5];
#pragma unroll
                    for (int r = 0; r < 5; ++r)
#pragma unroll
                        for (int c = 0; c < 5; ++c) {
                            float v = s1s[ic * 65 + (y0b + r) * 8 + (x0b + c)];
                            ins[r][c] = pk2(v, v);
                        }
#pragma unroll
                    for (int kk = 0; kk < 9; ++kk) {
                        const int ky = kk / 3, kx = kk % 3;
                        const u64t w = *(const u64t*)(w2p + ((ic * 9 + kk) * 32 + p) * 2);
#pragma unroll
                        for (int dy = 0; dy < 3; ++dy)
#pragma unroll
                            for (int dx = 0; dx < 3; ++dx)
                                acc2[dy * 3 + dx] = fma2(ins[dy + ky][dx + kx], w,
                                                         acc2[dy * 3 + dx]);
                    }
                }
            }
        }

        // ---------- A: conv2 LIF + pool -> g_pp[s&1] ----------
        if (doA) {
#pragma unroll
            for (int j = 0; j < 9; ++j) {
                const int dy = j / 3, dx = j % 3;
                float alo, ahi; upk2(acc2[j], alo, ahi);
#pragma unroll
                for (int o = 0; o < 2; ++o) {
                    const int occ = 2 * p + o;
                    const float psp = __fadd_rn(o ? ahi : alo, b2s[occ]);
                    lif_update(psp, c2[o][j], v2[o][j], sp2[o][j]);
                    s2s[occ * 36 + (y0b + dy) * 6 + (x0b + dx)] = sp2[o][j];
                }
            }
            __syncthreads();
            for (int idx = tid; idx < 576; idx += 128) {
                int c = idx / 9, pos = idx - c * 9;
                int py = pos / 3, px = pos - py * 3;
                float v = 0.25f * ((s2s[c * 36 + (2 * py) * 6 + 2 * px]
                                  + s2s[c * 36 + (2 * py) * 6 + 2 * px + 1])
                                 + (s2s[c * 36 + (2 * py + 1) * 6 + 2 * px]
                                  + s2s[c * 36 + (2 * py + 1) * 6 + 2 * px + 1]));
                int k = (h * 64 + c) * 9 + pos;
                g_pp[(size_t)(s & 1) * 73728 + (size_t)(k >> 2) * 256 + bA * 4 + (k & 3)] = v;
            }
        }

        // ---------- B: conv3 LIF + spike store ----------
        if (doB) {
            lif_update(__fadd_rn(a3, b3s[ol]), cur3, volt3, spk3);
            g_s3b[(size_t)(tB % 3) * 16384 + bB * 256 + rowB] = spk3;
        }
        gridbar_g(grp, 16);   // ---- bar 1 ----

        // ---------- B: tc (3 taps) + rec ----------
        if (doB) {
            const float* x0 = g_s3b + (size_t)(tB % 3) * 16384 + bB * 256;
            const float* x1 = g_s3b + (size_t)((tB + 2) % 3) * 16384 + bB * 256;
            const float* x2 = g_s3b + (size_t)((tB + 1) % 3) * 16384 + bB * 256;
            const float* w0 = tcw + (size_t)rowB * 256;
            const float* w1v = tcw + 65536 + (size_t)rowB * 256;
            const float* w2v = tcw + 131072 + (size_t)rowB * 256;
            const bool h1 = (tB >= 1), h2 = (tB >= 2);
            float d0 = 0.f, d1 = 0.f, d2 = 0.f;
#pragma unroll 8
            for (int k4 = 0; k4 < 64; ++k4) {
                float4 a0 = __ldcg((const float4*)(x0 + k4 * 4));
                float4 q0 = __ldcg((const float4*)(w0 + k4 * 4));
                d0 = __fmaf_rn(q0.x, a0.x, d0); d0 = __fmaf_rn(q0.y, a0.y, d0);
                d0 = __fmaf_rn(q0.z, a0.z, d0); d0 = __fmaf_rn(q0.w, a0.w, d0);
                if (h1) {
                    float4 a1 = __ldcg((const float4*)(x1 + k4 * 4));
                    float4 q1 = __ldcg((const float4*)(w1v + k4 * 4));
                    d1 = __fmaf_rn(q1.x, a1.x, d1); d1 = __fmaf_rn(q1.y, a1.y, d1);
                    d1 = __fmaf_rn(q1.z, a1.z, d1); d1 = __fmaf_rn(q1.w, a1.w, d1);
                }
                if (h2) {
                    float4 a2 = __ldcg((const float4*)(x2 + k4 * 4));
                    float4 q2 = __ldcg((const float4*)(w2v + k4 * 4));
                    d2 = __fmaf_rn(q2.x, a2.x, d2); d2 = __fmaf_rn(q2.y, a2.y, d2);
                    d2 = __fmaf_rn(q2.z, a2.z, d2); d2 = __fmaf_rn(q2.w, a2.w, d2);
                }
            }
            float a = __fadd_rn(0.f, __fadd_rn(d0, tcbs[ol]));
            if (h1) a = __fadd_rn(a, __fadd_rn(d1, tcbs[16 + ol]));
            if (h2) a = __fadd_rn(a, __fadd_rn(d2, tcbs[32 + ol]));
            lif_update(a, curt, voltt, spkt);

            float dotr = 0.f;
            if (tB > 0) {
                const float* xr = g_srb + (size_t)((tB & 1) ^ 1) * 16384 + bB * 256;
                const float* wr = recw + (size_t)rowB * 256;
#pragma unroll 8
                for (int k4 = 0; k4 < 64; ++k4) {
                    float4 x = __ldcg((const float4*)(xr + k4 * 4));
                    float4 w = __ldcg((const float4*)(wr + k4 * 4));
                    dotr = __fmaf_rn(w.x, x.x, dotr);
                    dotr = __fmaf_rn(w.y, x.y, dotr);
                    dotr = __fmaf_rn(w.z, x.z, dotr);
                    dotr = __fmaf_rn(w.w, x.w, dotr);
                }
            }
            const float pr = __fadd_rn(__fadd_rn(spkt, dotr), recbs[ol]);
            lif_update(pr, curr, voltr, spkr);
            g_srb[(size_t)(tB & 1) * 16384 + bB * 256 + rowB] = spkr;
        }
        gridbar_g(grp, 16);   // ---- bar 2 ----

        // ---------- B: fc1 (og<8) / fc2(tB-1) (og15) ----------
        if (doB) {
            if (og < 8) {
                const float* xr = g_srb + (size_t)(tB & 1) * 16384 + bB * 256;
                const float* wr = f1w + (size_t)rowB * 256;
                float d = 0.f;
#pragma unroll 8
                for (int k4 = 0; k4 < 64; ++k4) {
                    float4 x = __ldcg((const float4*)(xr + k4 * 4));
                    float4 w = __ldcg((const float4*)(wr + k4 * 4));
                    d = __fmaf_rn(w.x, x.x, d);
                    d = __fmaf_rn(w.y, x.y, d);
                    d = __fmaf_rn(w.z, x.z, d);
                    d = __fmaf_rn(w.w, x.w, d);
                }
                lif_update(__fadd_rn(d, f1bs[ol]), curf, voltf, spkf);
                g_sfb[(size_t)(tB & 1) * 8192 + bB * 128 + rowB] = spkf;
            } else if (og == 15 && tid < 16 && tB >= 1) {
                const int o = tid >> 3, bb = grp * 8 + (tid & 7);
                const float* xr = g_sfb + (size_t)((tB - 1) & 1) * 8192 + bb * 128;
                const float* wr = f2s + o * 128;
                float d = 0.f;
#pragma unroll 8
                for (int k4 = 0; k4 < 32; ++k4) {
                    float4 x = __ldcg((const float4*)(xr + k4 * 4));
                    float4 w = *(const float4*)(wr + k4 * 4);
                    d = __fmaf_rn(w.x, x.x, d);
                    d = __fmaf_rn(w.y, x.y, d);
                    d = __fmaf_rn(w.z, x.z, d);
                    d = __fmaf_rn(w.w, x.w, d);
                }
                outacc = __fadd_rn(outacc, __fmul_rn(d, tsws[tB - 1]));
            }
        }
    }

    gridbar_g(grp, 16);   // order fc1(199) writes
    if (og == 15 && tid < 16) {
        const int o = tid >> 3, bb = grp * 8 + (tid & 7);
        const float* xr = g_sfb + (size_t)((T_STEPS - 1) & 1) * 8192 + bb * 128;
        const float* wr = f2s + o * 128;
        float d = 0.f;
#pragma unroll 8
        for (int k4 = 0; k4 < 32; ++k4) {
            float4 x = __ldcg((const float4*)(xr + k4 * 4));
            float4 w = *(const float4*)(wr + k4 * 4);
            d = __fmaf_rn(w.x, x.x, d);
            d = __fmaf_rn(w.y, x.y, d);
            d = __fmaf_rn(w.z, x.z, d);
            d = __fmaf_rn(w.w, x.w, d);
        }
        outacc = __fadd_rn(outacc, __fmul_rn(d, tsws[T_STEPS - 1]));
        out[bb * 2 + o] = outacc;
    }
}

extern "C" void kernel_launch(void* const* d_in, const int* in_sizes, int n_in,
                              void* d_out, int out_size)
{
    (void)in_sizes; (void)n_in; (void)out_size;
    const float* input = (const float*)d_in[0];
    const float* w1 = (const float*)d_in[1];
    const float* b1 = (const float*)d_in[2];
    const float* w2 = (const float*)d_in[3];
    const float* b2 = (const float*)d_in[4];
    const float* w3 = (const float*)d_in[5];
    const float* b3 = (const float*)d_in[6];
    const float* tcw = (const float*)d_in[7];
    const float* tcb = (const float*)d_in[8];
    const float* recw = (const float*)d_in[9];
    const float* recb = (const float*)d_in[10];
    const float* f1w = (const float*)d_in[11];
    const float* f1b = (const float*)d_in[12];
    const float* f2w = (const float*)d_in[13];
    const float* tsw = (const float*)d_in[14];
    float* out = (float*)d_out;

    cudaFuncSetAttribute(fused_kernel, cudaFuncAttributeMaxDynamicSharedMemorySize,
                         S_TOT * sizeof(float));
    fused_kernel<<<128, 128, S_TOT * sizeof(float)>>>(input, w1, b1, w2, b2,
                                                      w3, b3, tcw, tcb, recw, recb,
                                                      f1w, f1b, f2w, tsw, out);
}

// round 12
// speedup vs baseline: 1.0009x; 1.0009x over previous
#include <cuda_runtime.h>
#include <cstdint>
#define T_STEPS 200
typedef unsigned long long u64t;

// ---------------- device scratch ----------------
__device__ float g_pp[2 * 288 * 64 * 4];      // pooled acts, 2 slots [slot][k4][b][4]
__device__ float g_s3b[3 * 64 * 256];          // conv3 spikes [slot][b][oc]
__device__ float g_srb[2 * 64 * 256];          // rec spikes   [buf][b][oc]
__device__ float g_sfb[2 * 64 * 128];          // fc1 spikes   [buf][b][row]
__device__ unsigned g_cnt[8 * 32];
__device__ unsigned g_gen[8 * 32];

__device__ __forceinline__ void gridbar_g(int grp, unsigned n) {
    __syncthreads();
    if (threadIdx.x == 0) {
        unsigned* cnt = &g_cnt[grp * 32];
        unsigned* gen = &g_gen[grp * 32];
        unsigned g;
        asm volatile("ld.acquire.gpu.u32 %0, [%1];" : "=r"(g) : "l"(gen));
        unsigned prev;
        asm volatile("atom.acq_rel.gpu.add.u32 %0, [%1], 1;"
                     : "=r"(prev) : "l"(cnt) : "memory");
        if (prev == n - 1u) {
            asm volatile("st.relaxed.gpu.u32 [%0], %1;" :: "l"(cnt), "r"(0u) : "memory");
            asm volatile("st.release.gpu.u32 [%0], %1;" :: "l"(gen), "r"(g + 1u) : "memory");
        } else {
            unsigned cur;
            do {
                asm volatile("ld.acquire.gpu.u32 %0, [%1];" : "=r"(cur) : "l"(gen));
            } while (cur == g);
        }
    }
    __syncthreads();
}
__device__ __forceinline__ u64t pk2(float lo, float hi) {
    u64t r; asm("mov.b64 %0, {%1, %2};" : "=l"(r) : "f"(lo), "f"(hi)); return r;
}
__device__ __forceinline__ void upk2(u64t v, float& lo, float& hi) {
    asm("mov.b64 {%0, %1}, %2;" : "=f"(lo), "=f"(hi) : "l"(v));
}
__device__ __forceinline__ u64t fma2(u64t a, u64t b, u64t c) {
    u64t d; asm("fma.rn.f32x2 %0, %1, %2, %3;" : "=l"(d) : "l"(a), "l"(b), "l"(c)); return d;
}
__device__ __forceinline__ void lif_update(float psp, float& cur, float& volt, float& spk) {
    cur  = __fadd_rn(__fmul_rn(0.5f, cur), psp);
    volt = __fadd_rn(__fmul_rn(__fmul_rn(0.75f, volt), __fadd_rn(1.f, -spk)), cur);
    spk  = (volt > 0.5f) ? 1.f : 0.f;
}

// ---------------- SMEM layout (floats) ----------------
#define S_XS    0        // 100
#define S_W1S   100      // 576
#define S_B1S   676      // 64
#define S_B2S   740      // 64
#define S_S1S   804      // 4160
#define S_S2S   4964     // 2304
#define S_W2P   7268     // 36864
#define S_B3    44132    // 16
#define S_TCB   44148    // 48
#define S_RECB  44196    // 16
#define S_F1B   44212    // 16
#define S_F2S   44228    // 256
#define S_TSW   44484    // 200
#define S_TOT   44684    // 178736 bytes

// ============================================================================
// Fused kernel: 128 CTAs x 128 threads.  Group g = CTAs [16g,16g+16).
// A-role: (b = 8g + (c16>>1), h = c16&1)   B-role: (og = c16, b-tile [8g,8g+8))
// Iteration s: phaseA(t=s) overlapped with phaseB conv3(t=s-1); then barriers,
// tc/rec(t=s-1), fc1(t=s-1), fc2(t=s-2).
// ============================================================================
__global__ __launch_bounds__(128, 1)
void fused_kernel(const float* __restrict__ input,
                  const float* __restrict__ w1, const float* __restrict__ b1,
                  const float* __restrict__ w2, const float* __restrict__ b2,
                  const float* __restrict__ w3, const float* __restrict__ b3,
                  const float* __restrict__ tcw, const float* __restrict__ tcb,
                  const float* __restrict__ recw, const float* __restrict__ recb,
                  const float* __restrict__ f1w, const float* __restrict__ f1b,
                  const float* __restrict__ f2w, const float* __restrict__ tsw,
                  float* __restrict__ out)
{
    extern __shared__ float sm[];
    float* xs   = sm + S_XS;
    float* w1s  = sm + S_W1S;
    float* b1s  = sm + S_B1S;
    float* b2s  = sm + S_B2S;
    float* s1s  = sm + S_S1S;
    float* s2s  = sm + S_S2S;
    float* w2p  = sm + S_W2P;
    float* b3s  = sm + S_B3;
    float* tcbs = sm + S_TCB;
    float* recbs= sm + S_RECB;
    float* f1bs = sm + S_F1B;
    float* f2s  = sm + S_F2S;
    float* tsws = sm + S_TSW;

    const int tid = threadIdx.x;
    const int cta = blockIdx.x;
    const int c16 = cta & 15, grp = cta >> 4;
    // A-role
    const int bA = grp * 8 + (c16 >> 1), h = c16 & 1;
    // B-role
    const int og = c16;
    const int ol = tid >> 3, blB = tid & 7;
    const int bB = grp * 8 + blB;
    const int rowB = og * 16 + ol;

    // ---- one-time staging ----
    for (int i = tid; i < 36864; i += 128) {
        int oc = i / 576, r = i - oc * 576;
        w2p[(r * 32 + (oc >> 1)) * 2 + (oc & 1)] = w2[h * 36864 + i];
    }
    for (int i = tid; i < 576; i += 128) w1s[i] = w1[i];
    if (tid < 64) { b1s[tid] = b1[tid]; b2s[tid] = b2[h * 64 + tid]; }
    for (int i = tid; i < 4160; i += 128) s1s[i] = 0.f;
    for (int i = tid; i < 2304; i += 128) s2s[i] = 0.f;
    if (tid < 16) {
        b3s[tid] = b3[og * 16 + tid];
        recbs[tid] = recb[og * 16 + tid];
        if (og < 8) f1bs[tid] = f1b[og * 16 + tid];
    }
    if (tid < 48) tcbs[tid] = tcb[(tid >> 4) * 256 + og * 16 + (tid & 15)];
    for (int i = tid; i < 256; i += 128) f2s[i] = f2w[i];
    for (int i = tid; i < 200; i += 128) tsws[i] = tsw[i];
    __syncthreads();

    // A LIF states (conv1 per 2 oc x 16 pos; conv2 per 2 oc x 9 pos)
    const int p = tid >> 2, q = tid & 3;
    const int qy = q >> 1, qx = q & 1;
    const int y0a = qy * 4, x0a = qx * 4, y0b = qy * 3, x0b = qx * 3;
    float c1[2][16], v1[2][16], c2[2][9], v2[2][9], sp2[2][9];
#pragma unroll
    for (int o = 0; o < 2; ++o) {
#pragma unroll
        for (int i = 0; i < 16; ++i) { c1[o][i] = 0.f; v1[o][i] = 0.f; }
#pragma unroll
        for (int i = 0; i < 9; ++i) { c2[o][i] = 0.f; v2[o][i] = 0.f; sp2[o][i] = 0.f; }
    }
    // B LIF states
    float cur3 = 0.f, volt3 = 0.f, spk3 = 0.f;
    float curt = 0.f, voltt = 0.f, spkt = 0.f;
    float curr = 0.f, voltr = 0.f, spkr = 0.f;
    float curf = 0.f, voltf = 0.f, spkf = 0.f;
    float outacc = 0.f;

    const float* xin = input + (size_t)bA * 20000;
    const float* wb3 = w3 + (size_t)rowB * 1152;

    for (int s = 0; s <= T_STEPS; ++s) {
        const int tB = s - 1;
        const bool doA = (s < T_STEPS);
        const bool doB = (tB >= 0);

        // ---------- A: frame + conv1 ----------
        if (doA) {
            if (tid < 100) xs[tid] = xin[tid * 200 + s];
            __syncthreads();
#pragma unroll
            for (int o = 0; o < 2; ++o) {
                const int occ = 2 * p + o;
                const float bb = b1s[occ];
                const float* wv = w1s + occ * 9;
#pragma unroll
                for (int iy = 0; iy < 4; ++iy)
#pragma unroll
                    for (int ix = 0; ix < 4; ++ix) {
                        const int y = y0a + iy, x = x0a + ix;
                        float a = 0.f;
#pragma unroll
                        for (int ky = 0; ky < 3; ++ky)
#pragma unroll
                            for (int kx = 0; kx < 3; ++kx)
                                a = __fmaf_rn(xs[(y + ky) * 10 + (x + kx)],
                                              wv[ky * 3 + kx], a);
                        const float psp = __fadd_rn(a, bb);
                        const int i = iy * 4 + ix, sidx = occ * 65 + y * 8 + x;
                        float sp = s1s[sidx];
                        lif_update(psp, c1[o][i], v1[o][i], sp);
                        s1s[sidx] = sp;
                    }
            }
            __syncthreads();
        }

        // ---------- fused conv2 (A) + conv3 (B): 8 interleaved blocks ----------
        float a3 = 0.f;
        const float* xb3 = g_pp + (size_t)(tB & 1) * 73728 + bB * 4;
        u64t acc2[9];
#pragma unroll
        for (int j = 0; j < 9; ++j) acc2[j] = 0ull;

        for (int blk = 0; blk < 8; ++blk) {
            // conv3 sub-block: 36 k4-groups, serial chain, L2-hot ldcg
            if (doB) {
#pragma unroll 6
                for (int k4 = blk * 36; k4 < blk * 36 + 36; ++k4) {
                    float4 x = __ldcg((const float4*)(xb3 + (size_t)k4 * 256));
                    float4 w = __ldcg((const float4*)(wb3 + k4 * 4));
                    a3 = __fmaf_rn(w.x, x.x, a3);
                    a3 = __fmaf_rn(w.y, x.y, a3);
                    a3 = __fmaf_rn(w.z, x.z, a3);
                    a3 = __fmaf_rn(w.w, x.w, a3);
                }
            }
            // conv2 sub-block: 8 ics (ascending -> chain order preserved)
            if (doA) {
#pragma unroll 2
                for (int ici = 0; ici < 8; ++ici) {
                    const int ic = blk * 8 + ici;
                    u64t ins[5][5];
#pragma unroll
                    for (int r = 0; r < 5; ++r)
#pragma unroll
                        for (int c = 0; c < 5; ++c) {
                            float v = s1s[ic * 65 + (y0b + r) * 8 + (x0b + c)];
                            ins[r][c] = pk2(v, v);
                        }
#pragma unroll
                    for (int kk = 0; kk < 9; ++kk) {
                        const int ky = kk / 3, kx = kk % 3;
                        const u64t w = *(const u64t*)(w2p + ((ic * 9 + kk) * 32 + p) * 2);
#pragma unroll
                        for (int dy = 0; dy < 3; ++dy)
#pragma unroll
                            for (int dx = 0; dx < 3; ++dx)
                                acc2[dy * 3 + dx] = fma2(ins[dy + ky][dx + kx], w,
                                                         acc2[dy * 3 + dx]);
                    }
                }
            }
        }

        // ---------- A: conv2 LIF + pool -> g_pp[s&1] ----------
        if (doA) {
#pragma unroll
            for (int j = 0; j < 9; ++j) {
                const int dy = j / 3, dx = j % 3;
                float alo, ahi; upk2(acc2[j], alo, ahi);
#pragma unroll
                for (int o = 0; o < 2; ++o) {
                    const int occ = 2 * p + o;
                    const float psp = __fadd_rn(o ? ahi : alo, b2s[occ]);
                    lif_update(psp, c2[o][j], v2[o][j], sp2[o][j]);
                    s2s[occ * 36 + (y0b + dy) * 6 + (x0b + dx)] = sp2[o][j];
                }
            }
            __syncthreads();
            for (int idx = tid; idx < 576; idx += 128) {
                int c = idx / 9, pos = idx - c * 9;
                int py = pos / 3, px = pos - py * 3;
                float v = 0.25f * ((s2s[c * 36 + (2 * py) * 6 + 2 * px]
                                  + s2s[c * 36 + (2 * py) * 6 + 2 * px + 1])
                                 + (s2s[c * 36 + (2 * py + 1) * 6 + 2 * px]
                                  + s2s[c * 36 + (2 * py + 1) * 6 + 2 * px + 1]));
                int k = (h * 64 + c) * 9 + pos;
                g_pp[(size_t)(s & 1) * 73728 + (size_t)(k >> 2) * 256 + bA * 4 + (k & 3)] = v;
            }
        }

        // ---------- B: conv3 LIF + spike store ----------
        if (doB) {
            lif_update(__fadd_rn(a3, b3s[ol]), cur3, volt3, spk3);
            g_s3b[(size_t)(tB % 3) * 16384 + bB * 256 + rowB] = spk3;
        }
        gridbar_g(grp, 16);   // ---- bar 1 ----

        // ---------- B: tc (3 taps) + rec ----------
        if (doB) {
            const float* x0 = g_s3b + (size_t)(tB % 3) * 16384 + bB * 256;
            const float* x1 = g_s3b + (size_t)((tB + 2) % 3) * 16384 + bB * 256;
            const float* x2 = g_s3b + (size_t)((tB + 1) % 3) * 16384 + bB * 256;
            const float* w0 = tcw + (size_t)rowB * 256;
            const float* w1v = tcw + 65536 + (size_t)rowB * 256;
            const float* w2v = tcw + 131072 + (size_t)rowB * 256;
            const bool h1 = (tB >= 1), h2 = (tB >= 2);
            float d0 = 0.f, d1 = 0.f, d2 = 0.f;
#pragma unroll 8
            for (int k4 = 0; k4 < 64; ++k4) {
                float4 a0 = __ldcg((const float4*)(x0 + k4 * 4));
                float4 q0 = __ldcg((const float4*)(w0 + k4 * 4));
                d0 = __fmaf_rn(q0.x, a0.x, d0); d0 = __fmaf_rn(q0.y, a0.y, d0);
                d0 = __fmaf_rn(q0.z, a0.z, d0); d0 = __fmaf_rn(q0.w, a0.w, d0);
                if (h1) {
                    float4 a1 = __ldcg((const float4*)(x1 + k4 * 4));
                    float4 q1 = __ldcg((const float4*)(w1v + k4 * 4));
                    d1 = __fmaf_rn(q1.x, a1.x, d1); d1 = __fmaf_rn(q1.y, a1.y, d1);
                    d1 = __fmaf_rn(q1.z, a1.z, d1); d1 = __fmaf_rn(q1.w, a1.w, d1);
                }
                if (h2) {
                    float4 a2 = __ldcg((const float4*)(x2 + k4 * 4));
                    float4 q2 = __ldcg((const float4*)(w2v + k4 * 4));
                    d2 = __fmaf_rn(q2.x, a2.x, d2); d2 = __fmaf_rn(q2.y, a2.y, d2);
                    d2 = __fmaf_rn(q2.z, a2.z, d2); d2 = __fmaf_rn(q2.w, a2.w, d2);
                }
            }
            float a = __fadd_rn(0.f, __fadd_rn(d0, tcbs[ol]));
            if (h1) a = __fadd_rn(a, __fadd_rn(d1, tcbs[16 + ol]));
            if (h2) a = __fadd_rn(a, __fadd_rn(d2, tcbs[32 + ol]));
            lif_update(a, curt, voltt, spkt);

            float dotr = 0.f;
            if (tB > 0) {
                const float* xr = g_srb + (size_t)((tB & 1) ^ 1) * 16384 + bB * 256;
                const float* wr = recw + (size_t)rowB * 256;
#pragma unroll 8
                for (int k4 = 0; k4 < 64; ++k4) {
                    float4 x = __ldcg((const float4*)(xr + k4 * 4));
                    float4 w = __ldcg((const float4*)(wr + k4 * 4));
                    dotr = __fmaf_rn(w.x, x.x, dotr);
                    dotr = __fmaf_rn(w.y, x.y, dotr);
                    dotr = __fmaf_rn(w.z, x.z, dotr);
                    dotr = __fmaf_rn(w.w, x.w, dotr);
                }
            }
            const float pr = __fadd_rn(__fadd_rn(spkt, dotr), recbs[ol]);
            lif_update(pr, curr, voltr, spkr);
            g_srb[(size_t)(tB & 1) * 16384 + bB * 256 + rowB] = spkr;
        }
        gridbar_g(grp, 16);   // ---- bar 2 ----

        // ---------- B: fc1 (og<8) / fc2(tB-1) (og15) ----------
        if (doB) {
            if (og < 8) {
                const float* xr = g_srb + (size_t)(tB & 1) * 16384 + bB * 256;
                const float* wr = f1w + (size_t)rowB * 256;
                float d = 0.f;
#pragma unroll 8
                for (int k4 = 0; k4 < 64; ++k4) {
                    float4 x = __ldcg((const float4*)(xr + k4 * 4));
                    float4 w = __ldcg((const float4*)(wr + k4 * 4));
                    d = __fmaf_rn(w.x, x.x, d);
                    d = __fmaf_rn(w.y, x.y, d);
                    d = __fmaf_rn(w.z, x.z, d);
                    d = __fmaf_rn(w.w, x.w, d);
                }
                lif_update(__fadd_rn(d, f1bs[ol]), curf, voltf, spkf);
                g_sfb[(size_t)(tB & 1) * 8192 + bB * 128 + rowB] = spkf;
            } else if (og == 15 && tid < 16 && tB >= 1) {
                const int o = tid >> 3, bb = grp * 8 + (tid & 7);
                const float* xr = g_sfb + (size_t)((tB - 1) & 1) * 8192 + bb * 128;
                const float* wr = f2s + o * 128;
                float d = 0.f;
#pragma unroll 8
                for (int k4 = 0; k4 < 32; ++k4) {
                    float4 x = __ldcg((const float4*)(xr + k4 * 4));
                    float4 w = *(const float4*)(wr + k4 * 4);
                    d = __fmaf_rn(w.x, x.x, d);
                    d = __fmaf_rn(w.y, x.y, d);
                    d = __fmaf_rn(w.z, x.z, d);
                    d = __fmaf_rn(w.w, x.w, d);
                }
                outacc = __fadd_rn(outacc, __fmul_rn(d, tsws[tB - 1]));
            }
        }
    }

    gridbar_g(grp, 16);   // order fc1(199) writes
    if (og == 15 && tid < 16) {
        const int o = tid >> 3, bb = grp * 8 + (tid & 7);
        const float* xr = g_sfb + (size_t)((T_STEPS - 1) & 1) * 8192 + bb * 128;
        const float* wr = f2s + o * 128;
        float d = 0.f;
#pragma unroll 8
        for (int k4 = 0; k4 < 32; ++k4) {
            float4 x = __ldcg((const float4*)(xr + k4 * 4));
            float4 w = *(const float4*)(wr + k4 * 4);
            d = __fmaf_rn(w.x, x.x, d);
            d = __fmaf_rn(w.y, x.y, d);
            d = __fmaf_rn(w.z, x.z, d);
            d = __fmaf_rn(w.w, x.w, d);
        }
        outacc = __fadd_rn(outacc, __fmul_rn(d, tsws[T_STEPS - 1]));
        out[bb * 2 + o] = outacc;
    }
}

extern "C" void kernel_launch(void* const* d_in, const int* in_sizes, int n_in,
                              void* d_out, int out_size)
{
    (void)in_sizes; (void)n_in; (void)out_size;
    const float* input = (const float*)d_in[0];
    const float* w1 = (const float*)d_in[1];
    const float* b1 = (const float*)d_in[2];
    const float* w2 = (const float*)d_in[3];
    const float* b2 = (const float*)d_in[4];
    const float* w3 = (const float*)d_in[5];
    const float* b3 = (const float*)d_in[6];
    const float* tcw = (const float*)d_in[7];
    const float* tcb = (const float*)d_in[8];
    const float* recw = (const float*)d_in[9];
    const float* recb = (const float*)d_in[10];
    const float* f1w = (const float*)d_in[11];
    const float* f1b = (const float*)d_in[12];
    const float* f2w = (const float*)d_in[13];
    const float* tsw = (const float*)d_in[14];
    float* out = (float*)d_out;

    cudaFuncSetAttribute(fused_kernel, cudaFuncAttributeMaxDynamicSharedMemorySize,
                         S_TOT * sizeof(float));
    fused_kernel<<<128, 128, S_TOT * sizeof(float)>>>(input, w1, b1, w2, b2,
                                                      w3, b3, tcw, tcb, recw, recb,
                                                      f1w, f1b, f2w, tsw, out);
}

// round 15
// speedup vs baseline: 1.2451x; 1.2439x over previous
#include <cuda_runtime.h>
#include <cstdint>
#define T_STEPS 200
typedef unsigned long long u64t;

// ---------------- device scratch ----------------
__device__ float g_pp[2 * 288 * 64 * 4];   // pooled acts [slot][k4][b][4]
__device__ float g_w2t[2 * 576 * 64];       // conv2 w transposed [h][(r*32+p)*2+(oc&1)]
__device__ float g_s3b[3 * 64 * 256];       // conv3 spikes [slot][b][oc]
__device__ float g_srb[2 * 64 * 256];       // rec spikes   [buf][b][oc]
__device__ float g_sfb[2 * 64 * 128];       // fc1 spikes   [buf][b][row]
__device__ unsigned g_cnt[16 * 32];
__device__ unsigned g_gen[16 * 32];

__device__ __forceinline__ void bar_A() { asm volatile("bar.sync 2, 128;" ::: "memory"); }
__device__ __forceinline__ void bar_B() { asm volatile("bar.sync 3, 128;" ::: "memory"); }

__device__ __forceinline__ void gb_core(int slot, unsigned n) {
    unsigned* cnt = &g_cnt[slot * 32];
    unsigned* gen = &g_gen[slot * 32];
    unsigned g;
    asm volatile("ld.acquire.gpu.u32 %0, [%1];" : "=r"(g) : "l"(gen));
    unsigned prev;
    asm volatile("atom.acq_rel.gpu.add.u32 %0, [%1], 1;" : "=r"(prev) : "l"(cnt) : "memory");
    if (prev == n - 1u) {
        asm volatile("st.relaxed.gpu.u32 [%0], %1;" :: "l"(cnt), "r"(0u) : "memory");
        asm volatile("st.release.gpu.u32 [%0], %1;" :: "l"(gen), "r"(g + 1u) : "memory");
    } else {
        unsigned cur;
        do { asm volatile("ld.acquire.gpu.u32 %0, [%1];" : "=r"(cur) : "l"(gen)); }
        while (cur == g);
    }
}
// full-CTA gridbar (A+B), counter slot grp
__device__ __forceinline__ void gridbar_full(int grp) {
    __syncthreads();
    if (threadIdx.x == 0) gb_core(grp, 16);
    __syncthreads();
}
// B-warps-only gridbar, counter slot 8+grp
__device__ __forceinline__ void gridbar_B(int grp) {
    bar_B();
    if (threadIdx.x == 128) gb_core(8 + grp, 16);
    bar_B();
}

__device__ __forceinline__ u64t pk2(float lo, float hi) {
    u64t r; asm("mov.b64 %0, {%1, %2};" : "=l"(r) : "f"(lo), "f"(hi)); return r;
}
__device__ __forceinline__ void upk2(u64t v, float& lo, float& hi) {
    asm("mov.b64 {%0, %1}, %2;" : "=f"(lo), "=f"(hi) : "l"(v));
}
__device__ __forceinline__ u64t fma2(u64t a, u64t b, u64t c) {
    u64t d; asm("fma.rn.f32x2 %0, %1, %2, %3;" : "=l"(d) : "l"(a), "l"(b), "l"(c)); return d;
}
__device__ __forceinline__ unsigned smem_u32(const void* p) {
    unsigned a;
    asm("{ .reg .u64 t; cvta.to.shared.u64 t, %1; cvt.u32.u64 %0, t; }" : "=r"(a) : "l"(p));
    return a;
}
__device__ __forceinline__ void cp16(unsigned sdst, const void* gsrc) {
    asm volatile("cp.async.cg.shared.global [%0], [%1], 16;" :: "r"(sdst), "l"(gsrc));
}
#define CP_COMMIT() asm volatile("cp.async.commit_group;" ::: "memory")
template<int N> __device__ __forceinline__ void cp_wait() {
    asm volatile("cp.async.wait_group %0;" :: "n"(N) : "memory");
}
__device__ __forceinline__ void lif_update(float psp, float& cur, float& volt, float& spk) {
    cur  = __fadd_rn(__fmul_rn(0.5f, cur), psp);
    volt = __fadd_rn(__fmul_rn(__fmul_rn(0.75f, volt), __fadd_rn(1.f, -spk)), cur);
    spk  = (volt > 0.5f) ? 1.f : 0.f;
}

// ---------------- SMEM layout (floats) ----------------
#define S_XS    0        // 100
#define S_W1S   100      // 576
#define S_B1S   676      // 64
#define S_B2S   740      // 64
#define S_S1S   804      // 4160
#define S_S2S   4964     // 2304
#define S_W3S   7268     // 18432  [k][16]
#define S_PB    25700    // 3*1024
#define S_B3    28772    // 16
#define S_TCB   28788    // 48
#define S_RECB  28836    // 16
#define S_F1B   28852    // 16
#define S_F2S   28868    // 256
#define S_TSW   29124    // 200
#define S_TOT   29324    // 117296 bytes

// one-shot conv2 weight transpose into g_w2t
__global__ void prep_kernel(const float* __restrict__ w2) {
    int i = blockIdx.x * 256 + threadIdx.x;
    if (i < 73728) {
        int h = i / 36864, r0 = i - h * 36864;
        int oc = r0 / 576, r = r0 - oc * 576;
        g_w2t[h * 36864 + (r * 32 + (oc >> 1)) * 2 + (oc & 1)] = w2[i];
    }
}

// ============================================================================
// Fused warp-specialized kernel: 128 CTAs x 256 threads.
// Group g = CTAs [16g,16g+16). A-warps tid<128: (bA=8g+(c16>>1), h=c16&1).
// B-warps tid>=128: og=c16, b-tile [8g,8g+8). Iteration s: A does t=s, B t=s-1.
// ============================================================================
__global__ __launch_bounds__(256, 1)
void fused_kernel(const float* __restrict__ input,
                  const float* __restrict__ w1, const float* __restrict__ b1,
                  const float* __restrict__ b2,
                  const float* __restrict__ w3, const float* __restrict__ b3,
                  const float* __restrict__ tcw, const float* __restrict__ tcb,
                  const float* __restrict__ recw, const float* __restrict__ recb,
                  const float* __restrict__ f1w, const float* __restrict__ f1b,
                  const float* __restrict__ f2w, const float* __restrict__ tsw,
                  float* __restrict__ out)
{
    extern __shared__ float sm[];
    float* xs   = sm + S_XS;
    float* w1s  = sm + S_W1S;
    float* b1s  = sm + S_B1S;
    float* b2s  = sm + S_B2S;
    float* s1s  = sm + S_S1S;
    float* s2s  = sm + S_S2S;
    float* w3s  = sm + S_W3S;
    float* pb   = sm + S_PB;
    float* b3s  = sm + S_B3;
    float* tcbs = sm + S_TCB;
    float* recbs= sm + S_RECB;
    float* f1bs = sm + S_F1B;
    float* f2s  = sm + S_F2S;
    float* tsws = sm + S_TSW;

    const int tid = threadIdx.x;
    const int cta = blockIdx.x;
    const int c16 = cta & 15, grp = cta >> 4;
    const int bA = grp * 8 + (c16 >> 1), h = c16 & 1;   // A-role
    const int og = c16;                                   // B-role
    const unsigned smb = smem_u32(sm);

    // ---- one-time staging (all 256 threads) ----
    for (int i = tid; i < 18432; i += 256)
        w3s[i] = w3[(size_t)(og * 16 + (i & 15)) * 1152 + (i >> 4)];
    for (int i = tid; i < 576; i += 256) w1s[i] = w1[i];
    if (tid < 64) { b1s[tid] = b1[tid]; b2s[tid] = b2[h * 64 + tid]; }
    for (int i = tid; i < 4160; i += 256) s1s[i] = 0.f;
    for (int i = tid; i < 2304; i += 256) s2s[i] = 0.f;
    if (tid < 16) {
        b3s[tid] = b3[og * 16 + tid];
        recbs[tid] = recb[og * 16 + tid];
        if (og < 8) f1bs[tid] = f1b[og * 16 + tid];
    }
    if (tid < 48) tcbs[tid] = tcb[(tid >> 4) * 256 + og * 16 + (tid & 15)];
    for (int i = tid; i < 256; i += 256) f2s[i] = f2w[i];
    for (int i = tid; i < 200; i += 256) tsws[i] = tsw[i];
    __syncthreads();

    // ---------- A-role state ----------
    const int p = tid >> 2, q = tid & 3;            // valid for tid<128
    const int qy = q >> 1, qx = q & 1;
    const int y0a = qy * 4, x0a = qx * 4, y0b = qy * 3, x0b = qx * 3;
    float c1[2][16], v1[2][16], c2[2][9], v2[2][9], sp2[2][9];
#pragma unroll
    for (int o = 0; o < 2; ++o) {
#pragma unroll
        for (int i = 0; i < 16; ++i) { c1[o][i] = 0.f; v1[o][i] = 0.f; }
#pragma unroll
        for (int i = 0; i < 9; ++i) { c2[o][i] = 0.f; v2[o][i] = 0.f; sp2[o][i] = 0.f; }
    }
    const float* xin = input + (size_t)bA * 20000;
    const float* w2g = g_w2t + h * 36864;

    // ---------- B-role state ----------
    const int btid = tid - 128;                      // valid for tid>=128
    const int ol = btid >> 3, blB = btid & 7;
    const int bB = grp * 8 + blB;
    const int rowB = og * 16 + ol;
    float cur3 = 0.f, volt3 = 0.f, spk3 = 0.f;
    float curt = 0.f, voltt = 0.f, spkt = 0.f;
    float curr = 0.f, voltr = 0.f, spkr = 0.f;
    float curf = 0.f, voltf = 0.f, spkf = 0.f;
    float outacc = 0.f;

    for (int s = 0; s <= T_STEPS; ++s) {
        const int tB = s - 1;

        if (tid < 128) {
            // ================= A-role: t = s =================
            if (s < T_STEPS) {
                if (tid < 100) xs[tid] = xin[tid * 200 + s];
                bar_A();
                // conv1
#pragma unroll
                for (int o = 0; o < 2; ++o) {
                    const int occ = 2 * p + o;
                    const float bb = b1s[occ];
                    const float* wv = w1s + occ * 9;
#pragma unroll
                    for (int iy = 0; iy < 4; ++iy)
#pragma unroll
                        for (int ix = 0; ix < 4; ++ix) {
                            const int y = y0a + iy, x = x0a + ix;
                            float a = 0.f;
#pragma unroll
                            for (int ky = 0; ky < 3; ++ky)
#pragma unroll
                                for (int kx = 0; kx < 3; ++kx)
                                    a = __fmaf_rn(xs[(y + ky) * 10 + (x + kx)],
                                                  wv[ky * 3 + kx], a);
                            const float psp = __fadd_rn(a, bb);
                            const int i = iy * 4 + ix, sidx = occ * 65 + y * 8 + x;
                            float sp = s1s[sidx];
                            lif_update(psp, c1[o][i], v1[o][i], sp);
                            s1s[sidx] = sp;
                        }
                }
                bar_A();
                // conv2: FFMA2 oc-pairs, weights streamed from L2
                u64t acc2[9];
#pragma unroll
                for (int j = 0; j < 9; ++j) acc2[j] = 0ull;
#pragma unroll 2
                for (int ic = 0; ic < 64; ++ic) {
                    u64t ins[5][5];
#pragma unroll
                    for (int r = 0; r < 5; ++r)
#pragma unroll
                        for (int c = 0; c < 5; ++c) {
                            float v = s1s[ic * 65 + (y0b + r) * 8 + (x0b + c)];
                            ins[r][c] = pk2(v, v);
                        }
#pragma unroll
                    for (int kk = 0; kk < 9; ++kk) {
                        const int ky = kk / 3, kx = kk % 3;
                        const u64t w = __ldcg((const u64t*)(w2g + ((ic * 9 + kk) * 32 + p) * 2));
#pragma unroll
                        for (int dy = 0; dy < 3; ++dy)
#pragma unroll
                            for (int dx = 0; dx < 3; ++dx)
                                acc2[dy * 3 + dx] = fma2(ins[dy + ky][dx + kx], w,
                                                         acc2[dy * 3 + dx]);
                    }
                }
#pragma unroll
                for (int j = 0; j < 9; ++j) {
                    const int dy = j / 3, dx = j % 3;
                    float alo, ahi; upk2(acc2[j], alo, ahi);
#pragma unroll
                    for (int o = 0; o < 2; ++o) {
                        const int occ = 2 * p + o;
                        const float psp = __fadd_rn(o ? ahi : alo, b2s[occ]);
                        lif_update(psp, c2[o][j], v2[o][j], sp2[o][j]);
                        s2s[occ * 36 + (y0b + dy) * 6 + (x0b + dx)] = sp2[o][j];
                    }
                }
                bar_A();
                // pool -> g_pp[s&1]
                for (int idx = tid; idx < 576; idx += 128) {
                    int c = idx / 9, pos = idx - c * 9;
                    int py = pos / 3, px = pos - py * 3;
                    float v = 0.25f * ((s2s[c * 36 + (2 * py) * 6 + 2 * px]
                                      + s2s[c * 36 + (2 * py) * 6 + 2 * px + 1])
                                     + (s2s[c * 36 + (2 * py + 1) * 6 + 2 * px]
                                      + s2s[c * 36 + (2 * py + 1) * 6 + 2 * px + 1]));
                    int k = (h * 64 + c) * 9 + pos;
                    g_pp[(size_t)(s & 1) * 73728 + (size_t)(k >> 2) * 256 + bA * 4 + (k & 3)] = v;
                }
            }
        } else if (tB >= 0) {
            // ================= B-role: t = tB =================
            const int slotP = tB & 1;
            auto stage = [&](int c, int buf) {
#pragma unroll
                for (int j = 0; j < 2; ++j) {
                    int idx = btid * 2 + j;          // 0..255 float4s
                    int k4l = idx >> 3, b2 = idx & 7;
                    const float* src = g_pp + (size_t)slotP * 73728
                                     + (size_t)(c * 32 + k4l) * 256 + (grp * 8 + b2) * 4;
                    unsigned dst = smb + (unsigned)(S_PB + buf * 1024 + (k4l * 8 + b2) * 4) * 4u;
                    cp16(dst, src);
                }
                CP_COMMIT();
            };
            stage(0, 0); stage(1, 1);
            float a3 = 0.f;
            for (int c = 0; c < 9; ++c) {
                if (c + 2 <= 8) cp_wait<1>(); else cp_wait<0>();
                bar_B();
                if (c + 2 <= 8) stage(c + 2, (c + 2) % 3);
                const float* xb = pb + (c % 3) * 1024;
                const float* wb = w3s + c * 128 * 16 + ol;
#pragma unroll
                for (int k4l = 0; k4l < 32; ++k4l) {
                    float4 x = *(const float4*)(xb + (k4l * 8 + blB) * 4);
                    a3 = __fmaf_rn(wb[(k4l * 4 + 0) * 16], x.x, a3);
                    a3 = __fmaf_rn(wb[(k4l * 4 + 1) * 16], x.y, a3);
                    a3 = __fmaf_rn(wb[(k4l * 4 + 2) * 16], x.z, a3);
                    a3 = __fmaf_rn(wb[(k4l * 4 + 3) * 16], x.w, a3);
                }
            }
            lif_update(__fadd_rn(a3, b3s[ol]), cur3, volt3, spk3);
            g_s3b[(size_t)(tB % 3) * 16384 + bB * 256 + rowB] = spk3;
            gridbar_B(grp);   // ---- B bar 1: s3 exchange ----

            // tc (3 taps) + rec
            {
                const float* x0 = g_s3b + (size_t)(tB % 3) * 16384 + bB * 256;
                const float* x1 = g_s3b + (size_t)((tB + 2) % 3) * 16384 + bB * 256;
                const float* x2 = g_s3b + (size_t)((tB + 1) % 3) * 16384 + bB * 256;
                const float* w0 = tcw + (size_t)rowB * 256;
                const float* w1v = tcw + 65536 + (size_t)rowB * 256;
                const float* w2v = tcw + 131072 + (size_t)rowB * 256;
                const bool h1 = (tB >= 1), h2 = (tB >= 2);
                float d0 = 0.f, d1 = 0.f, d2 = 0.f;
#pragma unroll 8
                for (int k4 = 0; k4 < 64; ++k4) {
                    float4 a0 = __ldcg((const float4*)(x0 + k4 * 4));
                    float4 q0 = *(const float4*)(w0 + k4 * 4);
                    d0 = __fmaf_rn(q0.x, a0.x, d0); d0 = __fmaf_rn(q0.y, a0.y, d0);
                    d0 = __fmaf_rn(q0.z, a0.z, d0); d0 = __fmaf_rn(q0.w, a0.w, d0);
                    if (h1) {
                        float4 a1 = __ldcg((const float4*)(x1 + k4 * 4));
                        float4 q1 = *(const float4*)(w1v + k4 * 4);
                        d1 = __fmaf_rn(q1.x, a1.x, d1); d1 = __fmaf_rn(q1.y, a1.y, d1);
                        d1 = __fmaf_rn(q1.z, a1.z, d1); d1 = __fmaf_rn(q1.w, a1.w, d1);
                    }
                    if (h2) {
                        float4 a2 = __ldcg((const float4*)(x2 + k4 * 4));
                        float4 q2 = *(const float4*)(w2v + k4 * 4);
                        d2 = __fmaf_rn(q2.x, a2.x, d2); d2 = __fmaf_rn(q2.y, a2.y, d2);
                        d2 = __fmaf_rn(q2.z, a2.z, d2); d2 = __fmaf_rn(q2.w, a2.w, d2);
                    }
                }
                float a = __fadd_rn(0.f, __fadd_rn(d0, tcbs[ol]));
                if (h1) a = __fadd_rn(a, __fadd_rn(d1, tcbs[16 + ol]));
                if (h2) a = __fadd_rn(a, __fadd_rn(d2, tcbs[32 + ol]));
                lif_update(a, curt, voltt, spkt);

                float dotr = 0.f;
                if (tB > 0) {
                    const float* xr = g_srb + (size_t)((tB & 1) ^ 1) * 16384 + bB * 256;
                    const float* wr = recw + (size_t)rowB * 256;
#pragma unroll 8
                    for (int k4 = 0; k4 < 64; ++k4) {
                        float4 x = __ldcg((const float4*)(xr + k4 * 4));
                        float4 w = *(const float4*)(wr + k4 * 4);
                        dotr = __fmaf_rn(w.x, x.x, dotr);
                        dotr = __fmaf_rn(w.y, x.y, dotr);
                        dotr = __fmaf_rn(w.z, x.z, dotr);
                        dotr = __fmaf_rn(w.w, x.w, dotr);
                    }
                }
                const float pr = __fadd_rn(__fadd_rn(spkt, dotr), recbs[ol]);
                lif_update(pr, curr, voltr, spkr);
                g_srb[(size_t)(tB & 1) * 16384 + bB * 256 + rowB] = spkr;
            }
            gridbar_B(grp);   // ---- B bar 2: sr exchange ----

            // fc1 (og<8) / fc2(tB-1) (og15)
            if (og < 8) {
                const float* xr = g_srb + (size_t)(tB & 1) * 16384 + bB * 256;
                const float* wr = f1w + (size_t)rowB * 256;
                float d = 0.f;
#pragma unroll 8
                for (int k4 = 0; k4 < 64; ++k4) {
                    float4 x = __ldcg((const float4*)(xr + k4 * 4));
                    float4 w = *(const float4*)(wr + k4 * 4);
                    d = __fmaf_rn(w.x, x.x, d);
                    d = __fmaf_rn(w.y, x.y, d);
                    d = __fmaf_rn(w.z, x.z, d);
                    d = __fmaf_rn(w.w, x.w, d);
                }
                lif_update(__fadd_rn(d, f1bs[ol]), curf, voltf, spkf);
                g_sfb[(size_t)(tB & 1) * 8192 + bB * 128 + rowB] = spkf;
            } else if (og == 15 && btid < 16 && tB >= 1) {
                const int o = btid >> 3, bb = grp * 8 + (btid & 7);
                const float* xr = g_sfb + (size_t)((tB - 1) & 1) * 8192 + bb * 128;
                const float* wr = f2s + o * 128;
                float d = 0.f;
#pragma unroll 8
                for (int k4 = 0; k4 < 32; ++k4) {
                    float4 x = __ldcg((const float4*)(xr + k4 * 4));
                    float4 w = *(const float4*)(wr + k4 * 4);
                    d = __fmaf_rn(w.x, x.x, d);
                    d = __fmaf_rn(w.y, x.y, d);
                    d = __fmaf_rn(w.z, x.z, d);
                    d = __fmaf_rn(w.w, x.w, d);
                }
                outacc = __fadd_rn(outacc, __fmul_rn(d, tsws[tB - 1]));
            }
        }

        gridbar_full(grp);   // ---- iteration-end: A(s) pool -> B(s+1) conv3 ----
    }

    // fc2(199): fc1(199) writes ordered by the last gridbar_full
    if (tid >= 128 && og == 15 && btid < 16) {
        const int o = btid >> 3, bb = grp * 8 + (btid & 7);
        const float* xr = g_sfb + (size_t)((T_STEPS - 1) & 1) * 8192 + bb * 128;
        const float* wr = f2s + o * 128;
        float d = 0.f;
#pragma unroll 8
        for (int k4 = 0; k4 < 32; ++k4) {
            float4 x = __ldcg((const float4*)(xr + k4 * 4));
            float4 w = *(const float4*)(wr + k4 * 4);
            d = __fmaf_rn(w.x, x.x, d);
            d = __fmaf_rn(w.y, x.y, d);
            d = __fmaf_rn(w.z, x.z, d);
            d = __fmaf_rn(w.w, x.w, d);
        }
        outacc = __fadd_rn(outacc, __fmul_rn(d, tsws[T_STEPS - 1]));
        out[bb * 2 + o] = outacc;
    }
}

extern "C" void kernel_launch(void* const* d_in, const int* in_sizes, int n_in,
                              void* d_out, int out_size)
{
    (void)in_sizes; (void)n_in; (void)out_size;
    const float* input = (const float*)d_in[0];
    const float* w1 = (const float*)d_in[1];
    const float* b1 = (const float*)d_in[2];
    const float* w2 = (const float*)d_in[3];
    const float* b2 = (const float*)d_in[4];
    const float* w3 = (const float*)d_in[5];
    const float* b3 = (const float*)d_in[6];
    const float* tcw = (const float*)d_in[7];
    const float* tcb = (const float*)d_in[8];
    const float* recw = (const float*)d_in[9];
    const float* recb = (const float*)d_in[10];
    const float* f1w = (const float*)d_in[11];
    const float* f1b = (const float*)d_in[12];
    const float* f2w = (const float*)d_in[13];
    const float* tsw = (const float*)d_in[14];
    float* out = (float*)d_out;

    prep_kernel<<<288, 256>>>(w2);
    cudaFuncSetAttribute(fused_kernel, cudaFuncAttributeMaxDynamicSharedMemorySize,
                         S_TOT * sizeof(float));
    fused_kernel<<<128, 256, S_TOT * sizeof(float)>>>(input, w1, b1, b2,
                                                      w3, b3, tcw, tcb, recw, recb,
                                                      f1w, f1b, f2w, tsw, out);
}